// round 13
// baseline (speedup 1.0000x reference)
#include <cuda_runtime.h>

#define BB 4
#define NN 8
#define HH 48
#define WW 48
#define HW (HH*WW)        /* 2304 */
#define TH 6
#define SMH (TH+6)
#define SMW (WW+6)        /* 54 */
#define BPIX (WW*TH)      /* 288 */
#define OUT_I_ELEMS (BB*NN*3*HW)   /* 221184 */
#define OUTM_ELEMS (BB*3*HW)       /* 27648  */
#define ZERO_TOT ((OUT_I_ELEMS + OUTM_ELEMS)/4)   /* 62208 float4 */

// Zero out_i + out_m, then fire the PDL trigger.
__global__ void zero_kernel(float4* __restrict__ p)
{
    int i = blockIdx.x * blockDim.x + threadIdx.x;
    if (i < ZERO_TOT) p[i] = make_float4(0.f, 0.f, 0.f, 0.f);
#if __CUDA_ARCH__ >= 900
    cudaTriggerProgrammaticLaunchCompletion();
#endif
}

// Fully decomposed rank-1 kernel-prediction apply (scalar, 1 px/thread —
// the R10 body: 71 regs, 3 blocks/SM, best measured compute time).
// One block = one (tile, color c, RGB t, n, b):
//   r = sum_s W[b,n,s,t] * S^c_{K(s)},  K(s)=7,5,3,1
//   S^c_K = sum_k c1[cur+k,c,t] * sum_l c2[cur+l,c,t] * F[c, h+k-3, w+l-3]
// 0.25*r atomically into pred_img_i, r/32 into pred_img.
// PDL: loads+compute overlap the zeroing kernel; griddep-sync only right
// before the first atomic.
__global__ __launch_bounds__(BPIX, 3)
void kpn_kernel(const float* __restrict__ frames,
                const float* __restrict__ core,
                const float* __restrict__ kw,
                float* __restrict__ out_i,
                float* __restrict__ out_m)
{
    const int gx   = blockIdx.x;        // 8 tiles * 12 (c,t)
    const int tile = gx / 12;
    const int ct   = gx - tile*12;
    const int c    = ct & 3;
    const int t    = ct >> 2;
    const int n    = blockIdx.y;
    const int b    = blockIdx.z;
    const int h0   = tile * TH;

    __shared__ float sF[SMH][SMW];      // one color, 648 floats

    const int tid = threadIdx.x;
    const int w   = tid % WW;
    const int ti  = tid / WW;
    const int pix = h0*WW + tid;        // contiguous: (h0+ti)*48 + w

    // ---- batch ALL global loads up front (36 LDG / thread) ----
    // core channel (within b,n): ch = q*12 + c*3 + t, stride HW.
    // Evict-first: the core stream is read exactly once; keep it from
    // displacing the reused kw/frames/output lines in L2.
    const float* cbase = core + ((size_t)b*3072 + (size_t)n*384
                                 + (size_t)(c*3 + t)) * HW + pix;
    float c1v[16], c2v[16];
    #pragma unroll
    for (int q = 0; q < 16; q++) {
        c1v[q] = __ldcs(&cbase[(size_t)( q    *12) * HW]);
        c2v[q] = __ldcs(&cbase[(size_t)((16+q)*12) * HW]);
    }
    // kernel_weight[b][n][s][t][h][w], s=0 pairs with K=7 (KS[::-1] stack)
    const float* wbp = kw + ((size_t)(b*NN + n))*12*HW + (size_t)t*HW + pix;
    float wb0 = wbp[0], wb1 = wbp[3*HW], wb2 = wbp[6*HW], wb3 = wbp[9*HW];

    // ---- frames tile for color c (zero-padded halo of 3) ----
    const float* fbase = frames + ((size_t)((b*NN + n)*4 + c)) * HW;
    #pragma unroll
    for (int k = 0; k < 3; k++) {       // 648 = 2.25 * 288
        int idx = k*BPIX + tid;
        if (idx < SMH*SMW) {
            int i  = idx / SMW;
            int j  = idx - i*SMW;
            int hh = h0 + i - 3;
            int wp = j - 3;
            float v = 0.f;
            if ((unsigned)hh < HH && (unsigned)wp < WW)
                v = fbase[hh*WW + wp];
            sF[i][j] = v;
        }
    }
    __syncthreads();

    // ---- 7-row walk; row i feeds K7 always, K5 rows 1..5, K3 rows 2..4,
    //      K1 row 3 ----
    float acc0 = 0.f, acc1 = 0.f, acc2 = 0.f, acc3 = 0.f;  // K1,K3,K5,K7
    #pragma unroll
    for (int i = 0; i < 7; i++) {
        float v[7];
        #pragma unroll
        for (int l = 0; l < 7; l++)
            v[l] = sF[ti + i][w + l];

        float rs7 = 0.f;
        #pragma unroll
        for (int l = 0; l < 7; l++)
            rs7 += c2v[9 + l] * v[l];
        acc3 += c1v[9 + i] * rs7;

        if (i >= 1 && i <= 5) {
            float rs5 = 0.f;
            #pragma unroll
            for (int l = 0; l < 5; l++)
                rs5 += c2v[4 + l] * v[1 + l];
            acc2 += c1v[4 + (i - 1)] * rs5;
        }
        if (i >= 2 && i <= 4) {
            float rs3 = c2v[1]*v[2] + c2v[2]*v[3] + c2v[3]*v[4];
            acc1 += c1v[1 + (i - 2)] * rs3;
        }
        if (i == 3)
            acc0 += c1v[0] * (c2v[0] * v[3]);
    }

    float r = wb0*acc3 + wb1*acc2 + wb2*acc1 + wb3*acc0;

#if __CUDA_ARCH__ >= 900
    cudaGridDependencySynchronize();     // zero_kernel done; safe to accumulate
#endif

    atomicAdd(out_i + ((size_t)(b*NN + n))*3*HW + (size_t)t*HW + pix,
              0.25f * r);
    atomicAdd(out_m + (size_t)b*3*HW + (size_t)t*HW + pix,
              0.03125f * r);              // 0.25 * (1/8)
}

extern "C" void kernel_launch(void* const* d_in, const int* in_sizes, int n_in,
                              void* d_out, int out_size)
{
    const float* frames = (const float*)d_in[0];
    const float* core   = (const float*)d_in[1];
    const float* kw     = (const float*)d_in[2];

    float* out   = (float*)d_out;
    float* out_i = out;                    // pred_img_i: (4,8,3,48,48)
    float* out_m = out + OUT_I_ELEMS;      // pred_img:   (4,3,48,48)

    zero_kernel<<<(ZERO_TOT + 255)/256, 256>>>((float4*)out);

    // PDL launch: kpn may begin while zero_kernel runs; it synchronizes on
    // the trigger only right before its atomics.
    cudaLaunchConfig_t cfg = {};
    cfg.gridDim  = dim3((HH/TH)*12, NN, BB);   // 96 x 8 x 4 = 3072 blocks
    cfg.blockDim = dim3(BPIX, 1, 1);
    cfg.dynamicSmemBytes = 0;
    cudaLaunchAttribute attrs[1];
    attrs[0].id = cudaLaunchAttributeProgrammaticStreamSerialization;
    attrs[0].val.programmaticStreamSerializationAllowed = 1;
    cfg.attrs = attrs;
    cfg.numAttrs = 1;

    cudaLaunchKernelEx(&cfg, kpn_kernel, frames, core, kw, out_i, out_m);
}

// round 14
// speedup vs baseline: 1.0764x; 1.0764x over previous
#include <cuda_runtime.h>

#define BB 4
#define NN 8
#define HH 48
#define WW 48
#define HW (HH*WW)        /* 2304 */
#define TH 2              /* rows per block tile */
#define SMH (TH+6)        /* 8 */
#define SMW (WW+6)        /* 54 */
#define SFN (SMH*SMW)     /* 432 */
#define NTHR (WW*TH)      /* 96 threads per block */
#define NTILES (HH/TH)    /* 24 */
#define OUT_I_ELEMS (BB*NN*3*HW)   /* 221184 */
#define OUTM_ELEMS (BB*3*HW)       /* 27648  */
#define ZERO_TOT ((OUT_I_ELEMS + OUTM_ELEMS)/4)   /* 62208 float4 */

// Zero out_i + out_m, then fire the PDL trigger.
__global__ void zero_kernel(float4* __restrict__ p)
{
    int i = blockIdx.x * blockDim.x + threadIdx.x;
    if (i < ZERO_TOT) p[i] = make_float4(0.f, 0.f, 0.f, 0.f);
#if __CUDA_ARCH__ >= 900
    cudaTriggerProgrammaticLaunchCompletion();
#endif
}

// Fully decomposed rank-1 kernel-prediction apply — many-small-blocks
// variant: 96-thread blocks (2-row tiles), 9 blocks/SM, so per-SM DRAM
// demand comes from 9 independently-staggered load phases instead of 3.
// One block = one (2-row tile, color c, RGB t, n, b):
//   r = sum_s W[b,n,s,t] * S^c_{K(s)},  K(s)=7,5,3,1
//   S^c_K = sum_k c1[cur+k,c,t] * sum_l c2[cur+l,c,t] * F[c, h+k-3, w+l-3]
// 0.25*r atomically into pred_img_i, r/32 into pred_img.
__global__ __launch_bounds__(NTHR, 9)
void kpn_kernel(const float* __restrict__ frames,
                const float* __restrict__ core,
                const float* __restrict__ kw,
                float* __restrict__ out_i,
                float* __restrict__ out_m)
{
    const int gx   = blockIdx.x;        // 24 tiles * 12 (c,t)
    const int tile = gx / 12;
    const int ct   = gx - tile*12;
    const int c    = ct & 3;
    const int t    = ct >> 2;
    const int n    = blockIdx.y;
    const int b    = blockIdx.z;
    const int h0   = tile * TH;

    __shared__ float sF[SMH][SMW];      // one color, 432 floats

    const int tid = threadIdx.x;
    const int w   = tid % WW;
    const int ti  = tid / WW;           // 0..1
    const int pix = h0*WW + tid;        // contiguous: (h0+ti)*48 + w

    // ---- batch ALL global loads up front (36 LDG / thread) ----
    // core channel (within b,n): ch = q*12 + c*3 + t, stride HW.
    // Evict-first: core stream is single-use.
    const float* cbase = core + ((size_t)b*3072 + (size_t)n*384
                                 + (size_t)(c*3 + t)) * HW + pix;
    float c1v[16], c2v[16];
    #pragma unroll
    for (int q = 0; q < 16; q++) {
        c1v[q] = __ldcs(&cbase[(size_t)( q    *12) * HW]);
        c2v[q] = __ldcs(&cbase[(size_t)((16+q)*12) * HW]);
    }
    // kernel_weight[b][n][s][t][h][w], s=0 pairs with K=7 (KS[::-1] stack)
    const float* wbp = kw + ((size_t)(b*NN + n))*12*HW + (size_t)t*HW + pix;
    float wb0 = wbp[0], wb1 = wbp[3*HW], wb2 = wbp[6*HW], wb3 = wbp[9*HW];

    // ---- frames tile for color c (zero-padded halo of 3) ----
    const float* fbase = frames + ((size_t)((b*NN + n)*4 + c)) * HW;
    #pragma unroll
    for (int k = 0; k < 5; k++) {       // 432 = 4.5 * 96
        int idx = k*NTHR + tid;
        if (idx < SFN) {
            int i  = idx / SMW;
            int j  = idx - i*SMW;
            int hh = h0 + i - 3;
            int wp = j - 3;
            float v = 0.f;
            if ((unsigned)hh < HH && (unsigned)wp < WW)
                v = fbase[hh*WW + wp];
            sF[i][j] = v;
        }
    }
    __syncthreads();

    // ---- 7-row walk; row i feeds K7 always, K5 rows 1..5, K3 rows 2..4,
    //      K1 row 3 ----
    float acc0 = 0.f, acc1 = 0.f, acc2 = 0.f, acc3 = 0.f;  // K1,K3,K5,K7
    #pragma unroll
    for (int i = 0; i < 7; i++) {
        float v[7];
        #pragma unroll
        for (int l = 0; l < 7; l++)
            v[l] = sF[ti + i][w + l];

        float rs7 = 0.f;
        #pragma unroll
        for (int l = 0; l < 7; l++)
            rs7 += c2v[9 + l] * v[l];
        acc3 += c1v[9 + i] * rs7;

        if (i >= 1 && i <= 5) {
            float rs5 = 0.f;
            #pragma unroll
            for (int l = 0; l < 5; l++)
                rs5 += c2v[4 + l] * v[1 + l];
            acc2 += c1v[4 + (i - 1)] * rs5;
        }
        if (i >= 2 && i <= 4) {
            float rs3 = c2v[1]*v[2] + c2v[2]*v[3] + c2v[3]*v[4];
            acc1 += c1v[1 + (i - 2)] * rs3;
        }
        if (i == 3)
            acc0 += c1v[0] * (c2v[0] * v[3]);
    }

    float r = wb0*acc3 + wb1*acc2 + wb2*acc1 + wb3*acc0;

#if __CUDA_ARCH__ >= 900
    cudaGridDependencySynchronize();     // zero_kernel done; safe to accumulate
#endif

    atomicAdd(out_i + ((size_t)(b*NN + n))*3*HW + (size_t)t*HW + pix,
              0.25f * r);
    atomicAdd(out_m + (size_t)b*3*HW + (size_t)t*HW + pix,
              0.03125f * r);              // 0.25 * (1/8)
}

extern "C" void kernel_launch(void* const* d_in, const int* in_sizes, int n_in,
                              void* d_out, int out_size)
{
    const float* frames = (const float*)d_in[0];
    const float* core   = (const float*)d_in[1];
    const float* kw     = (const float*)d_in[2];

    float* out   = (float*)d_out;
    float* out_i = out;                    // pred_img_i: (4,8,3,48,48)
    float* out_m = out + OUT_I_ELEMS;      // pred_img:   (4,3,48,48)

    zero_kernel<<<(ZERO_TOT + 255)/256, 256>>>((float4*)out);

    // PDL launch: kpn may begin while zero_kernel runs; it synchronizes on
    // the trigger only right before its atomics.
    cudaLaunchConfig_t cfg = {};
    cfg.gridDim  = dim3(NTILES*12, NN, BB);   // 288 x 8 x 4 = 9216 blocks
    cfg.blockDim = dim3(NTHR, 1, 1);
    cfg.dynamicSmemBytes = 0;
    cudaLaunchAttribute attrs[1];
    attrs[0].id = cudaLaunchAttributeProgrammaticStreamSerialization;
    attrs[0].val.programmaticStreamSerializationAllowed = 1;
    cfg.attrs = attrs;
    cfg.numAttrs = 1;

    cudaLaunchKernelEx(&cfg, kpn_kernel, frames, core, kw, out_i, out_m);
}